// round 1
// baseline (speedup 1.0000x reference)
#include <cuda_runtime.h>
#include <cuda_bf16.h>
#include <cstdint>

#define TQ    16384
#define DIN   1024
#define DOUT  1024
#define NE    8
#define BM    128
#define BN    128
#define BK    32
#define NKITER (DIN / BK)          // 32
#define MAXTILES (TQ / BM + NE)    // 136

// Padded smem strides (floats). Chosen for conflict-free MMA fragment LDS:
//   A stride 36  (36 mod 32 = 4): bank = 4*g + c  -> distinct over lane
//   B stride 136 (136 mod 32 = 8): bank = 8*c + g -> distinct over lane
#define AS_STRIDE (BK + 4)    // 36
#define BS_STRIDE (BN + 8)    // 136
#define SMEM_FLOATS (2 * BM * AS_STRIDE + 2 * BK * BS_STRIDE)
#define SMEM_BYTES  (SMEM_FLOATS * 4)   // 71680

// ---------------- scratch (device globals; no allocations) ----------------
__device__ int g_counts[NE];
__device__ int g_offsets[NE + 1];
__device__ int g_cursor[NE];
__device__ int g_perm[TQ];
__device__ int g_tile_expert[MAXTILES];
__device__ int g_tile_start[MAXTILES];

// ---------------- binning kernels ----------------
__global__ void k_init() {
    if (threadIdx.x < NE) g_counts[threadIdx.x] = 0;
}

__global__ void k_count(const int* __restrict__ idxs) {
    __shared__ int h[NE];
    if (threadIdx.x < NE) h[threadIdx.x] = 0;
    __syncthreads();
    int t = blockIdx.x * blockDim.x + threadIdx.x;
    if (t < TQ) atomicAdd(&h[idxs[t]], 1);
    __syncthreads();
    if (threadIdx.x < NE) atomicAdd(&g_counts[threadIdx.x], h[threadIdx.x]);
}

__global__ void k_scan() {
    if (threadIdx.x == 0) {
        int off = 0;
        for (int e = 0; e < NE; e++) {
            g_offsets[e] = off;
            g_cursor[e]  = off;
            off += g_counts[e];
        }
        g_offsets[NE] = off;
        int nt = 0;
        for (int e = 0; e < NE; e++) {
            for (int s = g_offsets[e]; s < g_offsets[e + 1]; s += BM) {
                g_tile_expert[nt] = e;
                g_tile_start[nt]  = s;
                nt++;
            }
        }
        for (; nt < MAXTILES; nt++) g_tile_expert[nt] = -1;
    }
}

__global__ void k_scatter(const int* __restrict__ idxs) {
    int t = blockIdx.x * blockDim.x + threadIdx.x;
    if (t < TQ) {
        int e = idxs[t];
        int p = atomicAdd(&g_cursor[e], 1);
        g_perm[p] = t;
    }
}

// ---------------- GEMM helpers ----------------
__device__ __forceinline__ void cp_async16(void* dst, const void* src) {
    uint32_t d = (uint32_t)__cvta_generic_to_shared(dst);
    asm volatile("cp.async.cg.shared.global [%0], [%1], 16;\n" :: "r"(d), "l"(src));
}

__device__ __forceinline__ void mma_tf32(float d[4], const uint32_t a[4], const uint32_t b[2]) {
    asm volatile(
        "mma.sync.aligned.m16n8k8.row.col.f32.tf32.tf32.f32 "
        "{%0,%1,%2,%3}, {%4,%5,%6,%7}, {%8,%9}, {%0,%1,%2,%3};\n"
        : "+f"(d[0]), "+f"(d[1]), "+f"(d[2]), "+f"(d[3])
        : "r"(a[0]), "r"(a[1]), "r"(a[2]), "r"(a[3]),
          "r"(b[0]), "r"(b[1]));
}

// ---------------- gather-GEMM: y[perm[r]] = relu(x[perm[r]] @ W[e] + b[e]) ----------------
__global__ __launch_bounds__(256, 2)
void k_gemm(const float* __restrict__ x, const float* __restrict__ W,
            const float* __restrict__ bias, float* __restrict__ y)
{
    const int tile = blockIdx.x;
    const int e = g_tile_expert[tile];
    if (e < 0) return;
    const int row0 = g_tile_start[tile];
    const int row_end = g_offsets[e + 1];
    const int n0 = blockIdx.y * BN;

    extern __shared__ float smem[];
    float* As_ = smem;                         // [2][BM][AS_STRIDE]
    float* Bs_ = smem + 2 * BM * AS_STRIDE;    // [2][BK][BS_STRIDE]
#define AS(b, m, k) As_[((b) * BM + (m)) * AS_STRIDE + (k)]
#define BS(b, k, n) Bs_[((b) * BK + (k)) * BS_STRIDE + (n)]

    const int tid  = threadIdx.x;
    const int lane = tid & 31;
    const int warp = tid >> 5;
    const int warpM = warp >> 2;     // 0..1  (64-row slab)
    const int warpN = warp & 3;      // 0..3  (32-col slab)
    const int grp = lane >> 2;       // 0..7
    const int c   = lane & 3;        // 0..3

    // Gathered token index per A-load row (constant across K loop)
    int tokenR[4];
#pragma unroll
    for (int i = 0; i < 4; i++) {
        int f = i * 256 + tid;
        int r = f >> 3;                    // row within tile
        int gr = row0 + r;
        tokenR[i] = g_perm[(gr < row_end) ? gr : (row_end - 1)];
    }

    const float* Wbase = W + (size_t)e * DIN * DOUT;

    auto prefetch = [&](int kt, int buf) {
        const int k0 = kt * BK;
#pragma unroll
        for (int i = 0; i < 4; i++) {
            int f = i * 256 + tid;
            int r = f >> 3, kc = (f & 7) * 4;
            cp_async16(&AS(buf, r, kc), x + (size_t)tokenR[i] * DIN + k0 + kc);
        }
#pragma unroll
        for (int i = 0; i < 4; i++) {
            int f = i * 256 + tid;
            int kr = f >> 5, nc = (f & 31) * 4;
            cp_async16(&BS(buf, kr, nc), Wbase + (size_t)(k0 + kr) * DOUT + n0 + nc);
        }
        asm volatile("cp.async.commit_group;\n" ::);
    };

    float acc[4][4][4] = {};   // [mi][nj][frag]

    prefetch(0, 0);
    for (int kt = 0; kt < NKITER; kt++) {
        const int buf = kt & 1;
        asm volatile("cp.async.wait_group 0;\n" ::);
        __syncthreads();
        if (kt + 1 < NKITER) prefetch(kt + 1, buf ^ 1);

#pragma unroll
        for (int ks = 0; ks < BK; ks += 8) {
            uint32_t af[4][4], bf[4][2];
#pragma unroll
            for (int mi = 0; mi < 4; mi++) {
                int m = warpM * 64 + mi * 16;
                af[mi][0] = __float_as_uint(AS(buf, m + grp,     ks + c));
                af[mi][1] = __float_as_uint(AS(buf, m + grp + 8, ks + c));
                af[mi][2] = __float_as_uint(AS(buf, m + grp,     ks + c + 4));
                af[mi][3] = __float_as_uint(AS(buf, m + grp + 8, ks + c + 4));
            }
#pragma unroll
            for (int nj = 0; nj < 4; nj++) {
                int n = warpN * 32 + nj * 8;
                bf[nj][0] = __float_as_uint(BS(buf, ks + c,     n + grp));
                bf[nj][1] = __float_as_uint(BS(buf, ks + c + 4, n + grp));
            }
#pragma unroll
            for (int mi = 0; mi < 4; mi++)
#pragma unroll
                for (int nj = 0; nj < 4; nj++)
                    mma_tf32(acc[mi][nj], af[mi], bf[nj]);
        }
        __syncthreads();
    }

    // Epilogue: bias + relu + scatter store
#pragma unroll
    for (int mi = 0; mi < 4; mi++) {
#pragma unroll
        for (int h = 0; h < 2; h++) {
            int mrow = warpM * 64 + mi * 16 + grp + h * 8;
            int gr = row0 + mrow;
            if (gr >= row_end) continue;
            int tok = g_perm[gr];
#pragma unroll
            for (int nj = 0; nj < 4; nj++) {
                int n = n0 + warpN * 32 + nj * 8 + 2 * c;
                float v0 = acc[mi][nj][h * 2 + 0] + bias[e * DOUT + n];
                float v1 = acc[mi][nj][h * 2 + 1] + bias[e * DOUT + n + 1];
                float2 out;
                out.x = fmaxf(v0, 0.0f);
                out.y = fmaxf(v1, 0.0f);
                *reinterpret_cast<float2*>(y + (size_t)tok * DOUT + n) = out;
            }
        }
    }
#undef AS
#undef BS
}

// ---------------- launch ----------------
extern "C" void kernel_launch(void* const* d_in, const int* in_sizes, int n_in,
                              void* d_out, int out_size) {
    const float* x    = (const float*)d_in[0];
    const int*   idxs = (const int*)  d_in[1];
    const float* W    = (const float*)d_in[2];
    const float* b    = (const float*)d_in[3];
    float* y = (float*)d_out;

    cudaFuncSetAttribute(k_gemm, cudaFuncAttributeMaxDynamicSharedMemorySize, SMEM_BYTES);

    k_init<<<1, 32>>>();
    k_count<<<TQ / 256, 256>>>(idxs);
    k_scan<<<1, 32>>>();
    k_scatter<<<TQ / 256, 256>>>(idxs);

    dim3 grid(MAXTILES, DOUT / BN);
    k_gemm<<<grid, 256, SMEM_BYTES>>>(x, W, b, y);
}